// round 1
// baseline (speedup 1.0000x reference)
#include <cuda_runtime.h>
#include <cstdint>

#define DEVI __device__ __forceinline__

constexpr int NQ = 131072;   // queries
constexpr int MN = 8192;     // tree nodes
constexpr float F_EPS = 1e-6f;
constexpr float F_BIG = 1e9f;

// ---------------- shared-memory layout (float offsets, 16B aligned) ----------
constexpr int OFF_W1 = 0;       // 2x100            (200)
constexpr int OFF_B1 = 200;     // 100               -> 300, pad to 304
constexpr int OFF_W2 = 304;     // 100x100           -> 10304
constexpr int OFF_B2 = 10304;   // 100               -> 10404, pad 10416
constexpr int OFF_W3 = 10416;   // 100x32 (rows padded 30->32) -> 13616
constexpr int OFF_B3 = 13616;   // 32                -> 13648
constexpr int OFF_W4 = 13648;   // 60 pad 64         -> 13712
constexpr int OFF_B4 = 13712;   // 2 pad 16          -> 13728
constexpr int OFF_H  = 13728;   // per-thread h row: 128 x 101
constexpr int H_STRIDE = 101;   // stride 101 -> conflict-free (gcd(101,32)=1)
constexpr int SMEM_FLOATS = OFF_H + 128 * H_STRIDE;
constexpr int SMEM_BYTES  = SMEM_FLOATS * 4;   // 106,624 B -> 2 CTAs/SM

// ---------------- scratch (device globals: no allocation allowed) ------------
__device__ float2 g_emb[MN];     // transformed node embeddings
__device__ float4 g_node2[MN];   // (prob2.x, prob2.y, has_child, 0)

typedef unsigned long long u64;

// ---------------- packed fp32x2 helpers (sm_100+ PTX) ------------------------
DEVI u64 pack2(float lo, float hi) {
    u64 r;
    asm("mov.b64 %0, {%1, %2};"
        : "=l"(r) : "r"(__float_as_uint(lo)), "r"(__float_as_uint(hi)));
    return r;
}
DEVI void unpack2(u64 v, float &lo, float &hi) {
    unsigned a, b;
    asm("mov.b64 {%0, %1}, %2;" : "=r"(a), "=r"(b) : "l"(v));
    lo = __uint_as_float(a); hi = __uint_as_float(b);
}
DEVI void fma2(u64 &d, u64 a, u64 b) {
    asm("fma.rn.f32x2 %0, %1, %2, %0;" : "+l"(d) : "l"(a), "l"(b));
}

// torch.nn.PairwiseDistance: ||a - b + eps||_2
DEVI float pdist(float ax, float ay, float bx, float by) {
    float dx = ax - bx + F_EPS;
    float dy = ay - by + F_EPS;
    return sqrtf(fmaf(dx, dx, dy * dy));
}

// ---------------- cooperative weight staging ---------------------------------
DEVI void load_weights(float* sm,
                       const float* W1, const float* b1,
                       const float* W2, const float* b2,
                       const float* W3, const float* b3,
                       const float* W4, const float* b4) {
    int t = threadIdx.x, nt = blockDim.x;
    for (int i = t; i < 50;   i += nt) ((float4*)(sm + OFF_W1))[i] = ((const float4*)W1)[i];
    for (int i = t; i < 25;   i += nt) ((float4*)(sm + OFF_B1))[i] = ((const float4*)b1)[i];
    for (int i = t; i < 2500; i += nt) ((float4*)(sm + OFF_W2))[i] = ((const float4*)W2)[i];
    for (int i = t; i < 25;   i += nt) ((float4*)(sm + OFF_B2))[i] = ((const float4*)b2)[i];
    for (int i = t; i < 3200; i += nt) {           // W3 rows padded 30 -> 32
        int k = i >> 5, j = i & 31;
        sm[OFF_W3 + i] = (j < 30) ? W3[k * 30 + j] : 0.f;
    }
    for (int i = t; i < 32; i += nt) sm[OFF_B3 + i] = (i < 30) ? b3[i] : 0.f;
    for (int i = t; i < 64; i += nt) sm[OFF_W4 + i] = (i < 60) ? W4[i] : 0.f;
    for (int i = t; i < 2;  i += nt) sm[OFF_B4 + i] = b4[i];
}

// ---------------- the MLP: 2 -> 100 -> 100 -> 30 -> 2 ------------------------
// h staged in the thread's private SMEM row; layer 2/3 in packed f32x2 with
// all-accumulators-resident (weights are warp-broadcast LDS.128).
DEVI float2 mlp_eval(float x0, float x1, const float* sm, float* hrow) {
    // layer 1 (2 -> 100)
    #pragma unroll
    for (int j = 0; j < 100; j += 4) {
        float4 w0 = *(const float4*)(sm + OFF_W1 + j);
        float4 w1 = *(const float4*)(sm + OFF_W1 + 100 + j);
        float4 bb = *(const float4*)(sm + OFF_B1 + j);
        hrow[j + 0] = fmaxf(fmaf(x0, w0.x, fmaf(x1, w1.x, bb.x)), 0.f);
        hrow[j + 1] = fmaxf(fmaf(x0, w0.y, fmaf(x1, w1.y, bb.y)), 0.f);
        hrow[j + 2] = fmaxf(fmaf(x0, w0.z, fmaf(x1, w1.z, bb.z)), 0.f);
        hrow[j + 3] = fmaxf(fmaf(x0, w0.w, fmaf(x1, w1.w, bb.w)), 0.f);
    }
    // layer 2 (100 -> 100), 50 packed accumulators
    u64 acc[50];
    #pragma unroll
    for (int p = 0; p < 50; p++) {
        float2 b = *(const float2*)(sm + OFF_B2 + 2 * p);
        acc[p] = pack2(b.x, b.y);
    }
    #pragma unroll 2
    for (int k = 0; k < 100; k++) {
        float hk = hrow[k];
        u64 hh = pack2(hk, hk);
        const float* wrow = sm + OFF_W2 + k * 100;
        #pragma unroll
        for (int p = 0; p < 25; p++) {
            ulonglong2 w = *(const ulonglong2*)(wrow + 4 * p);  // LDS.128 broadcast
            fma2(acc[2 * p + 0], hh, w.x);
            fma2(acc[2 * p + 1], hh, w.y);
        }
    }
    #pragma unroll
    for (int p = 0; p < 50; p++) {
        float a, b; unpack2(acc[p], a, b);
        hrow[2 * p + 0] = fmaxf(a, 0.f);
        hrow[2 * p + 1] = fmaxf(b, 0.f);
    }
    // layer 3 (100 -> 30), 15 packed accumulators
    u64 a3[15];
    #pragma unroll
    for (int p = 0; p < 15; p++) {
        float2 b = *(const float2*)(sm + OFF_B3 + 2 * p);
        a3[p] = pack2(b.x, b.y);
    }
    #pragma unroll 2
    for (int k = 0; k < 100; k++) {
        float hk = hrow[k];
        u64 hh = pack2(hk, hk);
        const float* wrow = sm + OFF_W3 + k * 32;
        #pragma unroll
        for (int p = 0; p < 7; p++) {
            ulonglong2 w = *(const ulonglong2*)(wrow + 4 * p);
            fma2(a3[2 * p + 0], hh, w.x);
            fma2(a3[2 * p + 1], hh, w.y);
        }
        u64 wl = *(const u64*)(wrow + 28);
        fma2(a3[14], hh, wl);
    }
    // layer 4 (30 -> 2)
    float o0 = sm[OFF_B4 + 0], o1 = sm[OFF_B4 + 1];
    #pragma unroll
    for (int p = 0; p < 15; p++) {
        float a, b; unpack2(a3[p], a, b);
        a = fmaxf(a, 0.f); b = fmaxf(b, 0.f);
        float4 w = *(const float4*)(sm + OFF_W4 + 4 * p); // W4[2p][0..1], W4[2p+1][0..1]
        o0 = fmaf(a, w.x, o0);
        o1 = fmaf(a, w.y, o1);
        o0 = fmaf(b, w.z, o0);
        o1 = fmaf(b, w.w, o1);
    }
    return make_float2(o0, o1);
}

// ---------------- traversal (per query, <=16 steps, stops at leaf) -----------
DEVI float2 traverse(float q0, float q1, const int4* __restrict__ ch4) {
    int cur = 0;
    float prob = 0.f, o0 = 0.f, o1 = 0.f;  // out stays zero if never stopping (matches ref)
    for (int t = 0; t < 16; t++) {
        int4 c0 = __ldg(ch4 + 2 * cur);
        int4 c1 = __ldg(ch4 + 2 * cur + 1);
        int ci[8] = {c0.x, c0.y, c0.z, c0.w, c1.x, c1.y, c1.z, c1.w};
        float2 e = g_emb[cur];
        float d0 = pdist(e.x, e.y, q0, q1);
        float d[8];
        #pragma unroll
        for (int k = 0; k < 8; k++) {
            int c = ci[k];
            if (c >= 0) {
                float2 ec = g_emb[c];
                d[k] = pdist(ec.x, ec.y, q0, q1);
            } else d[k] = F_BIG;
        }
        // argmax(log_softmax(-d)) == first-occurrence argmin(d)
        float best = d0; int bi = 0;
        #pragma unroll
        for (int k = 0; k < 8; k++) { if (d[k] < best) { best = d[k]; bi = k + 1; } }
        float S = expf(-(d0 - best));
        #pragma unroll
        for (int k = 0; k < 8; k++) S += expf(-(d[k] - best));  // invalid: exp(-1e9) == 0
        float mp = -logf(S);       // max of log_softmax
        prob += mp;
        if (t == 0) prob += mp;    // source quirk: first iteration adds max_prob twice
        if (bi == 0) {
            float4 n2 = g_node2[cur];
            if (n2.z != 0.f) { o0 = prob + n2.x; o1 = prob + n2.y; }
            else             { o0 = prob;        o1 = prob;        }
            break;
        }
        cur = ci[bi - 1];
    }
    return make_float2(o0, o1);
}

// ---------------- kernel 1: node MLP -> g_emb --------------------------------
__global__ void __launch_bounds__(128, 2)
node_mlp_kernel(const float* __restrict__ node_data,
                const float* __restrict__ W1, const float* __restrict__ b1,
                const float* __restrict__ W2, const float* __restrict__ b2,
                const float* __restrict__ W3, const float* __restrict__ b3,
                const float* __restrict__ W4, const float* __restrict__ b4) {
    extern __shared__ float sm[];
    load_weights(sm, W1, b1, W2, b2, W3, b3, W4, b4);
    __syncthreads();
    float* hrow = sm + OFF_H + threadIdx.x * H_STRIDE;
    int row = blockIdx.x * 128 + threadIdx.x;   // grid covers exactly MN rows
    float2 in = ((const float2*)node_data)[row];
    float2 o = mlp_eval(in.x, in.y, sm, hrow);
    g_emb[row] = o;
}

// ---------------- kernel 2: per-node prob2 / has_child (query-independent) ---
__global__ void precompute_kernel(const float* __restrict__ node_classes,
                                  const int* __restrict__ children) {
    int i = blockIdx.x * blockDim.x + threadIdx.x;
    if (i >= MN) return;
    const int4* ch4 = (const int4*)children;
    int4 c0 = ch4[2 * i], c1 = ch4[2 * i + 1];
    int ci[8] = {c0.x, c0.y, c0.z, c0.w, c1.x, c1.y, c1.z, c1.w};
    float2 e = g_emb[i];
    float d[8]; bool any = false;
    #pragma unroll
    for (int k = 0; k < 8; k++) {
        int c = ci[k];
        if (c >= 0) {
            float2 ec = g_emb[c];
            d[k] = pdist(e.x, e.y, ec.x, ec.y);   // dist(emb[cur], c_emb)
            any = true;
        } else d[k] = F_BIG;
    }
    float4 r = make_float4(0.f, 0.f, 0.f, 0.f);
    if (any) {
        float mn = d[0];
        #pragma unroll
        for (int k = 1; k < 8; k++) mn = fminf(mn, d[k]);
        float S = 0.f, m0 = 0.f, m1 = 0.f;
        #pragma unroll
        for (int k = 0; k < 8; k++) {
            float ek = expf(-(d[k] - mn));
            S += ek;
            int c = ci[k];
            if (c >= 0) {
                m0 = fmaf(ek, node_classes[2 * c + 0], m0);
                m1 = fmaf(ek, node_classes[2 * c + 1], m1);
            }
        }
        m0 /= S; m1 /= S;
        r.x = logf(fmaxf(m0, 1e-30f));
        r.y = logf(fmaxf(m1, 1e-30f));
        r.z = 1.f;
    }
    g_node2[i] = r;
}

// ---------------- kernel 3: query MLP + traversal, fused ---------------------
__global__ void __launch_bounds__(128, 2)
query_kernel(const float* __restrict__ x, const int* __restrict__ children,
             float* __restrict__ out,
             const float* __restrict__ W1, const float* __restrict__ b1,
             const float* __restrict__ W2, const float* __restrict__ b2,
             const float* __restrict__ W3, const float* __restrict__ b3,
             const float* __restrict__ W4, const float* __restrict__ b4) {
    extern __shared__ float sm[];
    load_weights(sm, W1, b1, W2, b2, W3, b3, W4, b4);
    __syncthreads();
    float* hrow = sm + OFF_H + threadIdx.x * H_STRIDE;
    const int4* ch4 = (const int4*)children;
    for (int row = blockIdx.x * 128 + threadIdx.x; row < NQ; row += gridDim.x * 128) {
        float2 in = ((const float2*)x)[row];
        float2 q = mlp_eval(in.x, in.y, sm, hrow);
        float2 o = traverse(q.x, q.y, ch4);
        ((float2*)out)[row] = o;
    }
}

// ---------------- launch ------------------------------------------------------
extern "C" void kernel_launch(void* const* d_in, const int* in_sizes, int n_in,
                              void* d_out, int out_size) {
    const float* x  = (const float*)d_in[0];
    const float* nd = (const float*)d_in[1];
    const float* nc = (const float*)d_in[2];
    const int*   ch = (const int*)  d_in[3];
    const float* W1 = (const float*)d_in[4];
    const float* b1 = (const float*)d_in[5];
    const float* W2 = (const float*)d_in[6];
    const float* b2 = (const float*)d_in[7];
    const float* W3 = (const float*)d_in[8];
    const float* b3 = (const float*)d_in[9];
    const float* W4 = (const float*)d_in[10];
    const float* b4 = (const float*)d_in[11];

    cudaFuncSetAttribute(node_mlp_kernel,
                         cudaFuncAttributeMaxDynamicSharedMemorySize, SMEM_BYTES);
    cudaFuncSetAttribute(query_kernel,
                         cudaFuncAttributeMaxDynamicSharedMemorySize, SMEM_BYTES);

    node_mlp_kernel<<<MN / 128, 128, SMEM_BYTES>>>(nd, W1, b1, W2, b2, W3, b3, W4, b4);
    precompute_kernel<<<MN / 256, 256>>>(nc, ch);
    query_kernel<<<NQ / 128, 128, SMEM_BYTES>>>(x, ch, (float*)d_out,
                                                W1, b1, W2, b2, W3, b3, W4, b4);
}

// round 2
// speedup vs baseline: 1.2758x; 1.2758x over previous
#include <cuda_runtime.h>
#include <cstdint>

#define DEVI __device__ __forceinline__

constexpr int NQ = 131072;   // queries
constexpr int MN = 8192;     // tree nodes
constexpr float F_EPS = 1e-6f;
constexpr float F_BIG = 1e9f;

// ---------------- shared-memory layout (float offsets) -----------------------
// W2 stored repacked as [100][104]: half0 cols at +0..49, half1 cols at +52..101
constexpr int OFF_W1 = 0;        // 2x100                 (200)
constexpr int OFF_B1 = 200;      // 100 -> 300, pad 304
constexpr int OFF_W2 = 304;      // 100x104 = 10400 -> 10704
constexpr int OFF_B2 = 10704;    // 100 -> 10804, pad 10816
constexpr int OFF_W3 = 10816;    // 100x32 (rows padded 30->32) -> 14016
constexpr int OFF_B3 = 14016;    // 32 -> 14048
constexpr int OFF_W4 = 14048;    // 60 pad 64 -> 14112
constexpr int OFF_B4 = 14112;    // 2 pad 16 -> 14128
constexpr int OFF_H  = 14128;    // per-PAIR h row: 256 x 101
constexpr int H_STRIDE = 101;    // odd stride -> conflict-free
constexpr int MLP_BLOCK = 512;   // 16 warps, 256 row-pairs
constexpr int MLP_GRID  = 152;   // GB300: 152 SMs, 1 CTA/SM (smem-bound)
constexpr int SMEM_FLOATS = OFF_H + (MLP_BLOCK / 2) * H_STRIDE;
constexpr int SMEM_BYTES  = SMEM_FLOATS * 4;   // 159,936 B

// ---------------- scratch (device globals: no allocation allowed) ------------
__device__ float2 g_emb[MN];     // transformed node embeddings
__device__ float2 g_qx[NQ];      // transformed queries
__device__ float4 g_node2[MN];   // (prob2.x, prob2.y, has_child, 0)

typedef unsigned long long u64;

// ---------------- packed fp32x2 helpers (sm_100+ PTX) ------------------------
DEVI u64 pack2(float lo, float hi) {
    u64 r;
    asm("mov.b64 %0, {%1, %2};"
        : "=l"(r) : "r"(__float_as_uint(lo)), "r"(__float_as_uint(hi)));
    return r;
}
DEVI void unpack2(u64 v, float &lo, float &hi) {
    unsigned a, b;
    asm("mov.b64 {%0, %1}, %2;" : "=r"(a), "=r"(b) : "l"(v));
    lo = __uint_as_float(a); hi = __uint_as_float(b);
}
DEVI void fma2(u64 &d, u64 a, u64 b) {
    asm("fma.rn.f32x2 %0, %1, %2, %0;" : "+l"(d) : "l"(a), "l"(b));
}

// torch.nn.PairwiseDistance: ||a - b + eps||_2
DEVI float pdist(float ax, float ay, float bx, float by) {
    float dx = ax - bx + F_EPS;
    float dy = ay - by + F_EPS;
    return sqrtf(fmaf(dx, dx, dy * dy));
}

// ---------------- cooperative weight staging ---------------------------------
DEVI void load_weights(float* sm,
                       const float* W1, const float* b1,
                       const float* W2, const float* b2,
                       const float* W3, const float* b3,
                       const float* W4, const float* b4) {
    int t = threadIdx.x, nt = blockDim.x;
    for (int i = t; i < 50;  i += nt) ((float4*)(sm + OFF_W1))[i] = ((const float4*)W1)[i];
    for (int i = t; i < 100; i += nt) sm[OFF_B1 + i] = b1[i];
    for (int i = t; i < 10000; i += nt) {          // repack W2 [100][100] -> [100][104]
        int k = i / 100, j = i - k * 100;
        int jj = (j < 50) ? j : (j + 2);
        sm[OFF_W2 + k * 104 + jj] = W2[i];
    }
    for (int i = t; i < 100; i += nt) sm[OFF_B2 + i] = b2[i];
    for (int i = t; i < 3200; i += nt) {           // W3 rows padded 30 -> 32
        int k = i >> 5, j = i & 31;
        sm[OFF_W3 + i] = (j < 30) ? W3[k * 30 + j] : 0.f;
    }
    for (int i = t; i < 32; i += nt) sm[OFF_B3 + i] = (i < 30) ? b3[i] : 0.f;
    for (int i = t; i < 64; i += nt) sm[OFF_W4 + i] = (i < 60) ? W4[i] : 0.f;
    for (int i = t; i < 16; i += nt) sm[OFF_B4 + i] = (i < 2) ? b4[i] : 0.f;
}

// ---------------- kernel 1: fused node+query MLP, pair-split -----------------
// One work unit = (row, half). Two lanes (2p, 2p+1) share a row: each computes
// half of layer-2 and layer-3 outputs; h exchanged via the pair's SMEM row;
// layer-4 partial sums pair-reduced with shfl.xor.
__global__ void __launch_bounds__(MLP_BLOCK, 1)
mlp_all_kernel(const float* __restrict__ x, const float* __restrict__ nd,
               const float* __restrict__ W1, const float* __restrict__ b1,
               const float* __restrict__ W2, const float* __restrict__ b2,
               const float* __restrict__ W3, const float* __restrict__ b3,
               const float* __restrict__ W4, const float* __restrict__ b4) {
    extern __shared__ float sm[];
    load_weights(sm, W1, b1, W2, b2, W3, b3, W4, b4);
    __syncthreads();

    const int tid  = threadIdx.x;
    const int half = tid & 1;
    float* hrow = sm + OFF_H + (tid >> 1) * H_STRIDE;

    const int TOTAL  = 2 * (MN + NQ);
    const int stride = MLP_GRID * MLP_BLOCK;
    const int rounds = (TOTAL + stride - 1) / stride;   // uniform across all threads
    int unit = blockIdx.x * MLP_BLOCK + tid;

    for (int r = 0; r < rounds; r++, unit += stride) {
        const bool active = unit < TOTAL;
        const int row = unit >> 1;

        // ---- layer 1 (2 -> 100): this lane fills its 50 h slots ----
        if (active) {
            float2 in = (row < MN) ? ((const float2*)nd)[row]
                                   : ((const float2*)x)[row - MN];
            const float x0 = in.x, x1 = in.y;
            const int jb = half * 50;
            #pragma unroll
            for (int j = 0; j < 50; j += 2) {
                float2 w0 = *(const float2*)(sm + OFF_W1 + jb + j);
                float2 w1 = *(const float2*)(sm + OFF_W1 + 100 + jb + j);
                float2 bb = *(const float2*)(sm + OFF_B1 + jb + j);
                hrow[jb + j + 0] = fmaxf(fmaf(x0, w0.x, fmaf(x1, w1.x, bb.x)), 0.f);
                hrow[jb + j + 1] = fmaxf(fmaf(x0, w0.y, fmaf(x1, w1.y, bb.y)), 0.f);
            }
        }
        __syncwarp();   // pair's full h1 row visible

        // ---- layer 2 (100 -> 100): this lane computes 50 outputs ----
        u64 acc[25];
        if (active) {
            #pragma unroll
            for (int p = 0; p < 25; p++) {
                float2 b = *(const float2*)(sm + OFF_B2 + half * 50 + 2 * p);
                acc[p] = pack2(b.x, b.y);
            }
            const float* w2base = sm + OFF_W2 + half * 52;
            #pragma unroll 1
            for (int k = 0; k < 100; k++) {
                const float hk = hrow[k];
                const u64 hh = pack2(hk, hk);
                const float* wr = w2base + k * 104;
                #pragma unroll
                for (int p = 0; p < 12; p++) {
                    ulonglong2 w = *(const ulonglong2*)(wr + 4 * p);  // LDS.128 bcast
                    fma2(acc[2 * p + 0], hh, w.x);
                    fma2(acc[2 * p + 1], hh, w.y);
                }
                u64 wl = *(const u64*)(wr + 48);
                fma2(acc[24], hh, wl);
            }
        }
        __syncwarp();   // all h1 reads done before overwriting with h2
        if (active) {
            const int jb = half * 50;
            #pragma unroll
            for (int p = 0; p < 25; p++) {
                float a, b; unpack2(acc[p], a, b);
                hrow[jb + 2 * p + 0] = fmaxf(a, 0.f);
                hrow[jb + 2 * p + 1] = fmaxf(b, 0.f);
            }
        }
        __syncwarp();   // pair's full h2 row visible

        // ---- layer 3 (100 -> 30, padded 32): this lane computes 16 outputs ----
        u64 a3[8];
        float o0 = 0.f, o1 = 0.f;
        if (active) {
            #pragma unroll
            for (int p = 0; p < 8; p++) {
                float2 b = *(const float2*)(sm + OFF_B3 + half * 16 + 2 * p);
                a3[p] = pack2(b.x, b.y);
            }
            const float* w3base = sm + OFF_W3 + half * 16;
            #pragma unroll 1
            for (int k = 0; k < 100; k++) {
                const float hk = hrow[k];
                const u64 hh = pack2(hk, hk);
                const float* wr = w3base + k * 32;
                #pragma unroll
                for (int p = 0; p < 4; p++) {
                    ulonglong2 w = *(const ulonglong2*)(wr + 4 * p);
                    fma2(a3[2 * p + 0], hh, w.x);
                    fma2(a3[2 * p + 1], hh, w.y);
                }
            }
            // ---- layer 4 (30 -> 2): partial sums over this lane's 16 h3 ----
            #pragma unroll
            for (int p = 0; p < 8; p++) {
                float a, b; unpack2(a3[p], a, b);
                a = fmaxf(a, 0.f); b = fmaxf(b, 0.f);
                float4 w = *(const float4*)(sm + OFF_W4 + half * 32 + 4 * p);
                o0 = fmaf(a, w.x, o0);
                o1 = fmaf(a, w.y, o1);
                o0 = fmaf(b, w.z, o0);
                o1 = fmaf(b, w.w, o1);
            }
        }
        // pair-reduce (shfl also orders h2 reads before next round's h1 writes)
        const float p0 = __shfl_xor_sync(0xffffffffu, o0, 1);
        const float p1 = __shfl_xor_sync(0xffffffffu, o1, 1);
        if (active && half == 0) {
            float2 o = make_float2(o0 + p0 + sm[OFF_B4 + 0],
                                   o1 + p1 + sm[OFF_B4 + 1]);
            if (row < MN) g_emb[row] = o;
            else          g_qx[row - MN] = o;
        }
        __syncwarp();
    }
}

// ---------------- kernel 2: per-node prob2 / has_child (query-independent) ---
__global__ void precompute_kernel(const float* __restrict__ node_classes,
                                  const int* __restrict__ children) {
    int i = blockIdx.x * blockDim.x + threadIdx.x;
    if (i >= MN) return;
    const int4* ch4 = (const int4*)children;
    int4 c0 = ch4[2 * i], c1 = ch4[2 * i + 1];
    int ci[8] = {c0.x, c0.y, c0.z, c0.w, c1.x, c1.y, c1.z, c1.w};
    float2 e = g_emb[i];
    float d[8]; bool any = false;
    #pragma unroll
    for (int k = 0; k < 8; k++) {
        int c = ci[k];
        if (c >= 0) {
            float2 ec = g_emb[c];
            d[k] = pdist(e.x, e.y, ec.x, ec.y);   // dist(emb[cur], c_emb)
            any = true;
        } else d[k] = F_BIG;
    }
    float4 r = make_float4(0.f, 0.f, 0.f, 0.f);
    if (any) {
        float mn = d[0];
        #pragma unroll
        for (int k = 1; k < 8; k++) mn = fminf(mn, d[k]);
        float S = 0.f, m0 = 0.f, m1 = 0.f;
        #pragma unroll
        for (int k = 0; k < 8; k++) {
            float ek = expf(-(d[k] - mn));
            S += ek;
            int c = ci[k];
            if (c >= 0) {
                m0 = fmaf(ek, node_classes[2 * c + 0], m0);
                m1 = fmaf(ek, node_classes[2 * c + 1], m1);
            }
        }
        m0 /= S; m1 /= S;
        r.x = logf(fmaxf(m0, 1e-30f));
        r.y = logf(fmaxf(m1, 1e-30f));
        r.z = 1.f;
    }
    g_node2[i] = r;
}

// ---------------- kernel 3: tree traversal (no smem, high occupancy) ---------
__global__ void __launch_bounds__(256)
traverse_kernel(const int* __restrict__ children, float* __restrict__ out) {
    const int q = blockIdx.x * 256 + threadIdx.x;   // grid covers NQ exactly
    const float2 qx = g_qx[q];
    const float q0 = qx.x, q1 = qx.y;
    const int4* ch4 = (const int4*)children;

    int cur = 0;
    float prob = 0.f, o0 = 0.f, o1 = 0.f;
    for (int t = 0; t < 16; t++) {
        int4 c0 = __ldg(ch4 + 2 * cur);
        int4 c1 = __ldg(ch4 + 2 * cur + 1);
        int ci[8] = {c0.x, c0.y, c0.z, c0.w, c1.x, c1.y, c1.z, c1.w};
        float2 e = g_emb[cur];
        float d0 = pdist(e.x, e.y, q0, q1);
        float d[8];
        #pragma unroll
        for (int k = 0; k < 8; k++) {
            int c = ci[k];
            if (c >= 0) {
                float2 ec = g_emb[c];
                d[k] = pdist(ec.x, ec.y, q0, q1);
            } else d[k] = F_BIG;
        }
        // argmax(log_softmax(-d)) == first-occurrence argmin(d)
        float best = d0; int bi = 0;
        #pragma unroll
        for (int k = 0; k < 8; k++) { if (d[k] < best) { best = d[k]; bi = k + 1; } }
        float S = __expf(-(d0 - best));
        #pragma unroll
        for (int k = 0; k < 8; k++) S += __expf(-(d[k] - best));  // pad: exp(-1e9)=0
        float mp = -__logf(S);     // max of log_softmax
        prob += mp;
        if (t == 0) prob += mp;    // source quirk: first iter adds max_prob twice
        if (bi == 0) {
            float4 n2 = g_node2[cur];
            if (n2.z != 0.f) { o0 = prob + n2.x; o1 = prob + n2.y; }
            else             { o0 = prob;        o1 = prob;        }
            break;
        }
        cur = ci[bi - 1];
    }
    ((float2*)out)[q] = make_float2(o0, o1);
}

// ---------------- launch ------------------------------------------------------
extern "C" void kernel_launch(void* const* d_in, const int* in_sizes, int n_in,
                              void* d_out, int out_size) {
    const float* x  = (const float*)d_in[0];
    const float* nd = (const float*)d_in[1];
    const float* nc = (const float*)d_in[2];
    const int*   ch = (const int*)  d_in[3];
    const float* W1 = (const float*)d_in[4];
    const float* b1 = (const float*)d_in[5];
    const float* W2 = (const float*)d_in[6];
    const float* b2 = (const float*)d_in[7];
    const float* W3 = (const float*)d_in[8];
    const float* b3 = (const float*)d_in[9];
    const float* W4 = (const float*)d_in[10];
    const float* b4 = (const float*)d_in[11];

    cudaFuncSetAttribute(mlp_all_kernel,
                         cudaFuncAttributeMaxDynamicSharedMemorySize, SMEM_BYTES);

    mlp_all_kernel<<<MLP_GRID, MLP_BLOCK, SMEM_BYTES>>>(x, nd,
                                                        W1, b1, W2, b2,
                                                        W3, b3, W4, b4);
    precompute_kernel<<<MN / 256, 256>>>(nc, ch);
    traverse_kernel<<<NQ / 256, 256>>>(ch, (float*)d_out);
}

// round 3
// speedup vs baseline: 1.5546x; 1.2185x over previous
#include <cuda_runtime.h>
#include <cstdint>

#define DEVI __device__ __forceinline__

constexpr int NQ = 131072;   // queries
constexpr int MN = 8192;     // tree nodes
constexpr float F_EPS = 1e-6f;
constexpr float F_BIG = 1e9f;

// ---------------- shared-memory layout (float word offsets) ------------------
// W2 repacked [100][112]: lane-quarter q owns cols [26q, 26q+26) at word 28q+jj
// W3 packed   [100][32] : lane-quarter q owns cols [8q, 8q+8)
constexpr int OFF_W1 = 0;        // [2][100]                    (200)
constexpr int OFF_B1 = 200;      // 100 -> 300, pad 304
constexpr int OFF_W2 = 304;      // 100*112 = 11200 -> 11504
constexpr int OFF_B2 = 11504;    // 112 -> 11616
constexpr int OFF_W3 = 11616;    // 100*32 = 3200 -> 14816
constexpr int OFF_B3 = 14816;    // 32 -> 14848
constexpr int OFF_W4 = 14848;    // [32][2] = 64 -> 14912
constexpr int OFF_B4 = 14912;    // 2 -> pad 14928
constexpr int OFF_H  = 14928;    // per-group h block: h4[k][4] rows-interleaved
constexpr int H_GSTRIDE = 404;   // 100*4 + 4 pad; 404%32=20 -> groups hit distinct banks
constexpr int GROUPS   = 96;     // 4-lane groups per CTA
constexpr int MLP_BLOCK = 384;   // 12 warps
constexpr int MLP_GRID  = 152;   // 1 CTA/SM
constexpr int SMEM_FLOATS = OFF_H + GROUPS * H_GSTRIDE;   // 53712
constexpr int SMEM_BYTES  = SMEM_FLOATS * 4;              // 214,848 B

constexpr int CHUNKS = (MN + NQ) / 4;   // 34816 four-row chunks (exact)

// ---------------- scratch (device globals: no allocation allowed) ------------
__device__ float2 g_emb[MN];     // transformed node embeddings
__device__ float2 g_qx[NQ];      // transformed queries
__device__ float4 g_node2[MN];   // (prob2.x, prob2.y, has_child, 0)

typedef unsigned long long u64;

// ---------------- packed fp32x2 helpers (sm_100+ PTX) ------------------------
DEVI u64 pack2(float lo, float hi) {
    u64 r;
    asm("mov.b64 %0, {%1, %2};"
        : "=l"(r) : "r"(__float_as_uint(lo)), "r"(__float_as_uint(hi)));
    return r;
}
DEVI void unpack2(u64 v, float &lo, float &hi) {
    unsigned a, b;
    asm("mov.b64 {%0, %1}, %2;" : "=r"(a), "=r"(b) : "l"(v));
    lo = __uint_as_float(a); hi = __uint_as_float(b);
}
DEVI void fma2(u64 &d, u64 a, u64 b) {
    asm("fma.rn.f32x2 %0, %1, %2, %0;" : "+l"(d) : "l"(a), "l"(b));
}

// torch.nn.PairwiseDistance: ||a - b + eps||_2
DEVI float pdist(float ax, float ay, float bx, float by) {
    float dx = ax - bx + F_EPS;
    float dy = ay - by + F_EPS;
    return sqrtf(fmaf(dx, dx, dy * dy));
}

// ---------------- kernel 1: fused node+query MLP ------------------------------
// Work unit = 4-row chunk handled by a 4-lane group. Lane q computes a 26-col
// slice of layers 2/3 for all 4 rows (register-blocked: weights loaded once,
// used 4x). h exchanged through the group's SMEM block, rows interleaved so one
// LDS.128 fetches all 4 rows' h[k]. Layer-4 reduced across lanes via shfl.xor.
__global__ void __launch_bounds__(MLP_BLOCK, 1)
mlp_all_kernel(const float* __restrict__ x, const float* __restrict__ nd,
               const float* __restrict__ W1, const float* __restrict__ b1,
               const float* __restrict__ W2, const float* __restrict__ b2,
               const float* __restrict__ W3, const float* __restrict__ b3,
               const float* __restrict__ W4, const float* __restrict__ b4) {
    extern __shared__ float sm[];
    const int t = threadIdx.x;

    // zero weight region (covers all pad slots), then fill
    for (int i = t; i < OFF_H; i += MLP_BLOCK) sm[i] = 0.f;
    __syncthreads();
    for (int i = t; i < 200; i += MLP_BLOCK) sm[OFF_W1 + i] = W1[i];
    for (int i = t; i < 100; i += MLP_BLOCK) sm[OFF_B1 + i] = b1[i];
    for (int i = t; i < 10000; i += MLP_BLOCK) {
        int k = i / 100, j = i - k * 100;
        int q = j / 26, jj = j - q * 26;
        sm[OFF_W2 + k * 112 + q * 28 + jj] = W2[i];
    }
    for (int j = t; j < 100; j += MLP_BLOCK) {
        int q = j / 26, jj = j - q * 26;
        sm[OFF_B2 + q * 28 + jj] = b2[j];
    }
    for (int i = t; i < 3000; i += MLP_BLOCK) {
        int k = i / 30, j = i - k * 30;
        sm[OFF_W3 + k * 32 + j] = W3[i];
    }
    for (int i = t; i < 30; i += MLP_BLOCK) sm[OFF_B3 + i] = b3[i];
    for (int i = t; i < 60; i += MLP_BLOCK) sm[OFF_W4 + i] = W4[i];
    if (t < 2) sm[OFF_B4 + t] = b4[t];
    __syncthreads();

    const int lane = t & 31;
    const int q = lane & 3;                        // column-slice id
    const int gid = (t >> 5) * 8 + (lane >> 2);    // group in CTA, 0..95
    float* hg = sm + OFF_H + gid * H_GSTRIDE;

    const float* w2p = sm + OFF_W2 + 28 * q;
    const float* w3p = sm + OFF_W3 + 8 * q;

    const int slots = MLP_GRID * GROUPS;                 // 14592
    const int rounds = (CHUNKS + slots - 1) / slots;     // 3 (uniform)
    int chunk = blockIdx.x * GROUPS + gid;

    for (int r = 0; r < rounds; r++, chunk += slots) {
        const bool active = chunk < CHUNKS;
        const int row0 = chunk * 4;

        // ---- layer 1 (2 -> 100): lane fills its col slice for all 4 rows ----
        float x0[4], x1[4];
        if (active) {
            const bool isnode = row0 < MN;   // MN%4==0: chunk never straddles
            const float2* src = isnode ? (const float2*)nd : (const float2*)x;
            const int base = isnode ? row0 : row0 - MN;
            #pragma unroll
            for (int rr = 0; rr < 4; rr++) {
                float2 v = src[base + rr];
                x0[rr] = v.x; x1[rr] = v.y;
            }
            #pragma unroll
            for (int jj = 0; jj < 26; jj++) {
                int j = 26 * q + jj;
                if (j < 100) {
                    float w0 = sm[OFF_W1 + j];
                    float w1 = sm[OFF_W1 + 100 + j];
                    float bb = sm[OFF_B1 + j];
                    float4 hv;
                    hv.x = fmaxf(fmaf(x0[0], w0, fmaf(x1[0], w1, bb)), 0.f);
                    hv.y = fmaxf(fmaf(x0[1], w0, fmaf(x1[1], w1, bb)), 0.f);
                    hv.z = fmaxf(fmaf(x0[2], w0, fmaf(x1[2], w1, bb)), 0.f);
                    hv.w = fmaxf(fmaf(x0[3], w0, fmaf(x1[3], w1, bb)), 0.f);
                    *(float4*)(hg + 4 * j) = hv;
                }
            }
        }
        __syncwarp();

        // ---- layer 2 (100 -> 100): 26 cols x 4 rows per lane ----
        u64 acc[52];
        if (active) {
            #pragma unroll
            for (int m = 0; m < 13; m++) {
                float2 bb = *(const float2*)(sm + OFF_B2 + 28 * q + 2 * m);
                u64 bv = pack2(bb.x, bb.y);
                acc[m] = bv; acc[13 + m] = bv; acc[26 + m] = bv; acc[39 + m] = bv;
            }
            #pragma unroll 1
            for (int k = 0; k < 100; k++) {
                float4 h4 = *(const float4*)(hg + 4 * k);
                u64 hh0 = pack2(h4.x, h4.x), hh1 = pack2(h4.y, h4.y);
                u64 hh2 = pack2(h4.z, h4.z), hh3 = pack2(h4.w, h4.w);
                const float* wr = w2p + k * 112;
                u64 wv[13];
                ulonglong2 wa = *(const ulonglong2*)(wr +  0);
                ulonglong2 wb = *(const ulonglong2*)(wr +  4);
                ulonglong2 wc = *(const ulonglong2*)(wr +  8);
                ulonglong2 wd = *(const ulonglong2*)(wr + 12);
                ulonglong2 we = *(const ulonglong2*)(wr + 16);
                ulonglong2 wf = *(const ulonglong2*)(wr + 20);
                wv[0] = wa.x; wv[1]  = wa.y; wv[2]  = wb.x; wv[3]  = wb.y;
                wv[4] = wc.x; wv[5]  = wc.y; wv[6]  = wd.x; wv[7]  = wd.y;
                wv[8] = we.x; wv[9]  = we.y; wv[10] = wf.x; wv[11] = wf.y;
                wv[12] = *(const u64*)(wr + 24);
                #pragma unroll
                for (int m = 0; m < 13; m++) {
                    fma2(acc[m],      hh0, wv[m]);
                    fma2(acc[13 + m], hh1, wv[m]);
                    fma2(acc[26 + m], hh2, wv[m]);
                    fma2(acc[39 + m], hh3, wv[m]);
                }
            }
        }
        __syncwarp();   // all lanes done reading h1 before overwriting with h2
        if (active) {
            #pragma unroll
            for (int m = 0; m < 13; m++) {
                int c0 = 26 * q + 2 * m;
                float a0, b0, a1, b1_, a2, b2_, a3, b3_;
                unpack2(acc[m],      a0, b0);
                unpack2(acc[13 + m], a1, b1_);
                unpack2(acc[26 + m], a2, b2_);
                unpack2(acc[39 + m], a3, b3_);
                if (c0 < 100) {
                    float4 v = make_float4(fmaxf(a0, 0.f), fmaxf(a1, 0.f),
                                           fmaxf(a2, 0.f), fmaxf(a3, 0.f));
                    *(float4*)(hg + 4 * c0) = v;
                }
                if (c0 + 1 < 100) {
                    float4 v = make_float4(fmaxf(b0, 0.f), fmaxf(b1_, 0.f),
                                           fmaxf(b2_, 0.f), fmaxf(b3_, 0.f));
                    *(float4*)(hg + 4 * (c0 + 1)) = v;
                }
            }
        }
        __syncwarp();

        // ---- layer 3 (100 -> 30 pad 32): 8 cols x 4 rows per lane ----
        u64 a3[16];
        float o0[4] = {0.f, 0.f, 0.f, 0.f};
        float o1[4] = {0.f, 0.f, 0.f, 0.f};
        if (active) {
            #pragma unroll
            for (int m = 0; m < 4; m++) {
                float2 bb = *(const float2*)(sm + OFF_B3 + 8 * q + 2 * m);
                u64 bv = pack2(bb.x, bb.y);
                a3[m] = bv; a3[4 + m] = bv; a3[8 + m] = bv; a3[12 + m] = bv;
            }
            #pragma unroll 2
            for (int k = 0; k < 100; k++) {
                float4 h4 = *(const float4*)(hg + 4 * k);
                u64 hh0 = pack2(h4.x, h4.x), hh1 = pack2(h4.y, h4.y);
                u64 hh2 = pack2(h4.z, h4.z), hh3 = pack2(h4.w, h4.w);
                const float* wr = w3p + k * 32;
                ulonglong2 wa = *(const ulonglong2*)(wr + 0);
                ulonglong2 wb = *(const ulonglong2*)(wr + 4);
                u64 wv[4] = {wa.x, wa.y, wb.x, wb.y};
                #pragma unroll
                for (int m = 0; m < 4; m++) {
                    fma2(a3[m],      hh0, wv[m]);
                    fma2(a3[4 + m],  hh1, wv[m]);
                    fma2(a3[8 + m],  hh2, wv[m]);
                    fma2(a3[12 + m], hh3, wv[m]);
                }
            }
            // ---- layer 4 (30 -> 2): partials over this lane's 8 cols ----
            #pragma unroll
            for (int m = 0; m < 4; m++) {
                int c = 8 * q + 2 * m;
                float2 wA = *(const float2*)(sm + OFF_W4 + 2 * c);
                float2 wB = *(const float2*)(sm + OFF_W4 + 2 * c + 2);
                #pragma unroll
                for (int rr = 0; rr < 4; rr++) {
                    float a, b;
                    unpack2(a3[rr * 4 + m], a, b);
                    a = fmaxf(a, 0.f); b = fmaxf(b, 0.f);
                    o0[rr] = fmaf(a, wA.x, o0[rr]);
                    o1[rr] = fmaf(a, wA.y, o1[rr]);
                    o0[rr] = fmaf(b, wB.x, o0[rr]);
                    o1[rr] = fmaf(b, wB.y, o1[rr]);
                }
            }
        }
        // reduce across the aligned 4-lane group (full-warp shfl, all threads)
        #pragma unroll
        for (int rr = 0; rr < 4; rr++) {
            o0[rr] += __shfl_xor_sync(0xffffffffu, o0[rr], 1);
            o0[rr] += __shfl_xor_sync(0xffffffffu, o0[rr], 2);
            o1[rr] += __shfl_xor_sync(0xffffffffu, o1[rr], 1);
            o1[rr] += __shfl_xor_sync(0xffffffffu, o1[rr], 2);
        }
        if (active) {
            // lane q emits row rr == q (static selects, no local-mem indexing)
            float s0 = (q == 0) ? o0[0] : (q == 1) ? o0[1] : (q == 2) ? o0[2] : o0[3];
            float s1 = (q == 0) ? o1[0] : (q == 1) ? o1[1] : (q == 2) ? o1[2] : o1[3];
            float2 ov = make_float2(s0 + sm[OFF_B4 + 0], s1 + sm[OFF_B4 + 1]);
            int row = row0 + q;
            if (row < MN) g_emb[row] = ov;
            else          g_qx[row - MN] = ov;
        }
        __syncwarp();
    }
}

// ---------------- kernel 2: per-node prob2 / has_child (query-independent) ---
__global__ void precompute_kernel(const float* __restrict__ node_classes,
                                  const int* __restrict__ children) {
    int i = blockIdx.x * blockDim.x + threadIdx.x;
    if (i >= MN) return;
    const int4* ch4 = (const int4*)children;
    int4 c0 = ch4[2 * i], c1 = ch4[2 * i + 1];
    int ci[8] = {c0.x, c0.y, c0.z, c0.w, c1.x, c1.y, c1.z, c1.w};
    float2 e = g_emb[i];
    float d[8]; bool any = false;
    #pragma unroll
    for (int k = 0; k < 8; k++) {
        int c = ci[k];
        if (c >= 0) {
            float2 ec = g_emb[c];
            d[k] = pdist(e.x, e.y, ec.x, ec.y);   // dist(emb[cur], c_emb)
            any = true;
        } else d[k] = F_BIG;
    }
    float4 r = make_float4(0.f, 0.f, 0.f, 0.f);
    if (any) {
        float mn = d[0];
        #pragma unroll
        for (int k = 1; k < 8; k++) mn = fminf(mn, d[k]);
        float S = 0.f, m0 = 0.f, m1 = 0.f;
        #pragma unroll
        for (int k = 0; k < 8; k++) {
            float ek = expf(-(d[k] - mn));
            S += ek;
            int c = ci[k];
            if (c >= 0) {
                m0 = fmaf(ek, node_classes[2 * c + 0], m0);
                m1 = fmaf(ek, node_classes[2 * c + 1], m1);
            }
        }
        m0 /= S; m1 /= S;
        r.x = logf(fmaxf(m0, 1e-30f));
        r.y = logf(fmaxf(m1, 1e-30f));
        r.z = 1.f;
    }
    g_node2[i] = r;
}

// ---------------- kernel 3: tree traversal (no smem, high occupancy) ---------
__global__ void __launch_bounds__(256)
traverse_kernel(const int* __restrict__ children, float* __restrict__ out) {
    const int q = blockIdx.x * 256 + threadIdx.x;   // grid covers NQ exactly
    const float2 qx = g_qx[q];
    const float q0 = qx.x, q1 = qx.y;
    const int4* ch4 = (const int4*)children;

    int cur = 0;
    float prob = 0.f, o0 = 0.f, o1 = 0.f;
    for (int t = 0; t < 16; t++) {
        int4 c0 = __ldg(ch4 + 2 * cur);
        int4 c1 = __ldg(ch4 + 2 * cur + 1);
        int ci[8] = {c0.x, c0.y, c0.z, c0.w, c1.x, c1.y, c1.z, c1.w};
        float2 e = g_emb[cur];
        float d0 = pdist(e.x, e.y, q0, q1);
        float d[8];
        #pragma unroll
        for (int k = 0; k < 8; k++) {
            int c = ci[k];
            if (c >= 0) {
                float2 ec = g_emb[c];
                d[k] = pdist(ec.x, ec.y, q0, q1);
            } else d[k] = F_BIG;
        }
        // argmax(log_softmax(-d)) == first-occurrence argmin(d)
        float best = d0; int bi = 0;
        #pragma unroll
        for (int k = 0; k < 8; k++) { if (d[k] < best) { best = d[k]; bi = k + 1; } }
        float S = __expf(-(d0 - best));
        #pragma unroll
        for (int k = 0; k < 8; k++) S += __expf(-(d[k] - best));  // pad: exp(-1e9)=0
        float mp = -__logf(S);     // max of log_softmax
        prob += mp;
        if (t == 0) prob += mp;    // source quirk: first iter adds max_prob twice
        if (bi == 0) {
            float4 n2 = g_node2[cur];
            if (n2.z != 0.f) { o0 = prob + n2.x; o1 = prob + n2.y; }
            else             { o0 = prob;        o1 = prob;        }
            break;
        }
        cur = ci[bi - 1];
    }
    ((float2*)out)[q] = make_float2(o0, o1);
}

// ---------------- launch ------------------------------------------------------
extern "C" void kernel_launch(void* const* d_in, const int* in_sizes, int n_in,
                              void* d_out, int out_size) {
    const float* x  = (const float*)d_in[0];
    const float* nd = (const float*)d_in[1];
    const float* nc = (const float*)d_in[2];
    const int*   ch = (const int*)  d_in[3];
    const float* W1 = (const float*)d_in[4];
    const float* b1 = (const float*)d_in[5];
    const float* W2 = (const float*)d_in[6];
    const float* b2 = (const float*)d_in[7];
    const float* W3 = (const float*)d_in[8];
    const float* b3 = (const float*)d_in[9];
    const float* W4 = (const float*)d_in[10];
    const float* b4 = (const float*)d_in[11];

    cudaFuncSetAttribute(mlp_all_kernel,
                         cudaFuncAttributeMaxDynamicSharedMemorySize, SMEM_BYTES);

    mlp_all_kernel<<<MLP_GRID, MLP_BLOCK, SMEM_BYTES>>>(x, nd,
                                                        W1, b1, W2, b2,
                                                        W3, b3, W4, b4);
    precompute_kernel<<<MN / 256, 256>>>(nc, ch);
    traverse_kernel<<<NQ / 256, 256>>>(ch, (float*)d_out);
}

// round 4
// speedup vs baseline: 1.6679x; 1.0729x over previous
#include <cuda_runtime.h>
#include <cstdint>

#define DEVI __device__ __forceinline__

constexpr int NQ = 131072;   // queries
constexpr int MN = 8192;     // tree nodes
constexpr float F_EPS = 1e-6f;
constexpr float F_BIG = 1e9f;

// ---------------- shared-memory layout (float word offsets) ------------------
constexpr int OFF_W1 = 0;        // [2][100]                       (200)
constexpr int OFF_B1 = 200;      // 100 -> 300, pad 304
constexpr int OFF_W2 = 304;      // [100][104] = 10400 -> 10704 (cols 100..103 zero)
constexpr int OFF_B2 = 10704;    // 104 -> 10808
constexpr int OFF_W3 = 10808;    // [100][32] = 3200 -> 14008 (cols 30,31 zero)
constexpr int OFF_B3 = 14008;    // 32 -> 14040
constexpr int OFF_W4 = 14040;    // [32][2] = 64 -> 14104
constexpr int OFF_B4 = 14104;    // 2 pad 8 -> 14112
constexpr int OFF_H  = 14112;    // per-group h block: [k][8 rows], 100*8 = 800
constexpr int H_GSTRIDE = 808;   // +8 pad; 808%32=8 -> warp's 4 groups hit distinct banks
constexpr int R_ROWS  = 8;       // rows per group
constexpr int GROUPS  = 40;      // 8-lane groups per CTA
constexpr int MLP_BLOCK = 320;   // 10 warps (4 groups per warp)
constexpr int MLP_GRID  = 152;
constexpr int SMEM_FLOATS = OFF_H + GROUPS * H_GSTRIDE;   // 46432
constexpr int SMEM_BYTES  = SMEM_FLOATS * 4;              // 185,728 B

constexpr int CHUNKS = (MN + NQ) / R_ROWS;   // 17408 eight-row chunks (exact)

// ---------------- scratch (device globals: no allocation allowed) ------------
__device__ float2 g_emb[MN];     // transformed node embeddings
__device__ float2 g_qx[NQ];      // transformed queries
__device__ float4 g_node2[MN];   // (prob2.x, prob2.y, has_child, 0)

typedef unsigned long long u64;

// ---------------- packed fp32x2 helpers (sm_100+ PTX) ------------------------
DEVI u64 pack2(float lo, float hi) {
    u64 r;
    asm("mov.b64 %0, {%1, %2};"
        : "=l"(r) : "r"(__float_as_uint(lo)), "r"(__float_as_uint(hi)));
    return r;
}
DEVI void unpack2(u64 v, float &lo, float &hi) {
    unsigned a, b;
    asm("mov.b64 {%0, %1}, %2;" : "=r"(a), "=r"(b) : "l"(v));
    lo = __uint_as_float(a); hi = __uint_as_float(b);
}
DEVI void fma2(u64 &d, u64 a, u64 b) {
    asm("fma.rn.f32x2 %0, %1, %2, %0;" : "+l"(d) : "l"(a), "l"(b));
}

// torch.nn.PairwiseDistance: ||a - b + eps||_2
DEVI float pdist(float ax, float ay, float bx, float by) {
    float dx = ax - bx + F_EPS;
    float dy = ay - by + F_EPS;
    return sqrtf(fmaf(dx, dx, dy * dy));
}

// ---------------- kernel 1: fused node+query MLP ------------------------------
// Work unit = 8-row chunk handled by an 8-lane group. Lane q owns layer-2 cols
// {2q+16j, 2q+16j+1 : j=0..5} (LDS.64 weight pairs) + singleton col 96+q, for
// all 8 rows (weights amortized 8x). h exchanged via the group's SMEM block
// ([k][8 rows], one LDS.128 pair per k). Layer-4 reduced over lanes via shfl.
__global__ void __launch_bounds__(MLP_BLOCK, 1)
mlp_all_kernel(const float* __restrict__ x, const float* __restrict__ nd,
               const float* __restrict__ W1, const float* __restrict__ b1,
               const float* __restrict__ W2, const float* __restrict__ b2,
               const float* __restrict__ W3, const float* __restrict__ b3,
               const float* __restrict__ W4, const float* __restrict__ b4) {
    extern __shared__ float sm[];
    const int t = threadIdx.x;

    // zero weight region (covers all pad slots), then fill (plain layouts)
    for (int i = t; i < OFF_H; i += MLP_BLOCK) sm[i] = 0.f;
    __syncthreads();
    for (int i = t; i < 200; i += MLP_BLOCK) sm[OFF_W1 + i] = W1[i];
    for (int i = t; i < 100; i += MLP_BLOCK) sm[OFF_B1 + i] = b1[i];
    for (int i = t; i < 10000; i += MLP_BLOCK) {
        int k = i / 100, j = i - k * 100;
        sm[OFF_W2 + k * 104 + j] = W2[i];
    }
    for (int j = t; j < 100; j += MLP_BLOCK) sm[OFF_B2 + j] = b2[j];
    for (int i = t; i < 3000; i += MLP_BLOCK) {
        int k = i / 30, j = i - k * 30;
        sm[OFF_W3 + k * 32 + j] = W3[i];
    }
    for (int i = t; i < 30; i += MLP_BLOCK) sm[OFF_B3 + i] = b3[i];
    for (int i = t; i < 60; i += MLP_BLOCK) sm[OFF_W4 + i] = W4[i];
    if (t < 2) sm[OFF_B4 + t] = b4[t];
    __syncthreads();

    const int lane = t & 31;
    const int q   = lane & 7;                   // lane within group
    const int gid = (t >> 5) * 4 + (lane >> 3); // group in CTA, 0..39
    float* hg = sm + OFF_H + gid * H_GSTRIDE;

    const int slots  = MLP_GRID * GROUPS;                // 6080
    const int rounds = (CHUNKS + slots - 1) / slots;     // 3 (uniform)
    int chunk = blockIdx.x * GROUPS + gid;

    for (int rnd = 0; rnd < rounds; rnd++, chunk += slots) {
        const bool active = chunk < CHUNKS;
        const int row0 = chunk * R_ROWS;

        // ---- layer 1 (2 -> 100): lane computes h1[kk][0..7] for its 13 k's --
        if (active) {
            const bool isnode = row0 < MN;   // MN%8==0: chunk never straddles
            const float2* src = isnode ? (const float2*)nd : (const float2*)x;
            const int base = isnode ? row0 : row0 - MN;
            float x0[8], x1[8];
            #pragma unroll
            for (int r = 0; r < 8; r++) {
                float2 v = src[base + r];
                x0[r] = v.x; x1[r] = v.y;
            }
            #pragma unroll
            for (int j = 0; j < 13; j++) {
                int kk = q + 8 * j;
                if (kk < 100) {
                    float wa = sm[OFF_W1 + kk];
                    float wb = sm[OFF_W1 + 100 + kk];
                    float bb = sm[OFF_B1 + kk];
                    float hv[8];
                    #pragma unroll
                    for (int r = 0; r < 8; r++)
                        hv[r] = fmaxf(fmaf(x0[r], wa, fmaf(x1[r], wb, bb)), 0.f);
                    *(float4*)(hg + kk * 8)     = make_float4(hv[0], hv[1], hv[2], hv[3]);
                    *(float4*)(hg + kk * 8 + 4) = make_float4(hv[4], hv[5], hv[6], hv[7]);
                }
            }
        }
        __syncwarp();

        // ---- layer 2 (100 -> 100): 6 col-pairs + 1 singleton, x 8 rows ------
        u64 acc[6][8];
        float sc[8];
        {
            #pragma unroll
            for (int j = 0; j < 6; j++) {
                u64 bv = *(const u64*)(sm + OFF_B2 + 2 * q + 16 * j);
                #pragma unroll
                for (int r = 0; r < 8; r++) acc[j][r] = bv;
            }
            float bs = sm[OFF_B2 + 96 + q];
            #pragma unroll
            for (int r = 0; r < 8; r++) sc[r] = bs;
        }
        const float* w2q = sm + OFF_W2 + 2 * q;
        const float* w2s = sm + OFF_W2 + 96 + q;
        #pragma unroll 2
        for (int k = 0; k < 100; k++) {
            const float* hk = hg + k * 8;
            float4 ha = *(const float4*)hk;
            float4 hb = *(const float4*)(hk + 4);
            float h8[8] = {ha.x, ha.y, ha.z, ha.w, hb.x, hb.y, hb.z, hb.w};
            u64 hh[8];
            #pragma unroll
            for (int r = 0; r < 8; r++) hh[r] = pack2(h8[r], h8[r]);
            const float* wr = w2q + k * 104;
            #pragma unroll
            for (int j = 0; j < 6; j++) {
                u64 w = *(const u64*)(wr + 16 * j);
                #pragma unroll
                for (int r = 0; r < 8; r++) fma2(acc[j][r], hh[r], w);
            }
            float wsv = w2s[k * 104];
            #pragma unroll
            for (int r = 0; r < 8; r++) sc[r] = fmaf(h8[r], wsv, sc[r]);
        }
        __syncwarp();   // all lanes done reading h1 before overwriting with h2

        // relu + write h2 back to the group's h block
        if (active) {
            #pragma unroll
            for (int j = 0; j < 6; j++) {
                float va[8], vb[8];
                #pragma unroll
                for (int r = 0; r < 8; r++) {
                    float a, b; unpack2(acc[j][r], a, b);
                    va[r] = fmaxf(a, 0.f); vb[r] = fmaxf(b, 0.f);
                }
                int c0 = 2 * q + 16 * j;
                *(float4*)(hg + c0 * 8)           = make_float4(va[0], va[1], va[2], va[3]);
                *(float4*)(hg + c0 * 8 + 4)       = make_float4(va[4], va[5], va[6], va[7]);
                *(float4*)(hg + (c0 + 1) * 8)     = make_float4(vb[0], vb[1], vb[2], vb[3]);
                *(float4*)(hg + (c0 + 1) * 8 + 4) = make_float4(vb[4], vb[5], vb[6], vb[7]);
            }
            if (q < 4) {   // singleton cols 96..99 (q>=4 hit zero pads, unused)
                float vs[8];
                #pragma unroll
                for (int r = 0; r < 8; r++) vs[r] = fmaxf(sc[r], 0.f);
                *(float4*)(hg + (96 + q) * 8)     = make_float4(vs[0], vs[1], vs[2], vs[3]);
                *(float4*)(hg + (96 + q) * 8 + 4) = make_float4(vs[4], vs[5], vs[6], vs[7]);
            }
        }
        __syncwarp();

        // ---- layer 3 (100 -> 30 pad 32): lane cols {2q,2q+1,2q+16,2q+17} ----
        u64 a3[2][8];
        {
            u64 b0 = *(const u64*)(sm + OFF_B3 + 2 * q);
            u64 b1v = *(const u64*)(sm + OFF_B3 + 2 * q + 16);
            #pragma unroll
            for (int r = 0; r < 8; r++) { a3[0][r] = b0; a3[1][r] = b1v; }
        }
        const float* w3q = sm + OFF_W3 + 2 * q;
        #pragma unroll 2
        for (int k = 0; k < 100; k++) {
            const float* hk = hg + k * 8;
            float4 ha = *(const float4*)hk;
            float4 hb = *(const float4*)(hk + 4);
            float h8[8] = {ha.x, ha.y, ha.z, ha.w, hb.x, hb.y, hb.z, hb.w};
            u64 hh[8];
            #pragma unroll
            for (int r = 0; r < 8; r++) hh[r] = pack2(h8[r], h8[r]);
            const float* wr = w3q + k * 32;
            u64 w0 = *(const u64*)(wr);
            u64 w1v = *(const u64*)(wr + 16);
            #pragma unroll
            for (int r = 0; r < 8; r++) {
                fma2(a3[0][r], hh[r], w0);
                fma2(a3[1][r], hh[r], w1v);
            }
        }

        // ---- layer 4 (30 -> 2): partials over this lane's 4 cols ------------
        float o0[8], o1[8];
        #pragma unroll
        for (int r = 0; r < 8; r++) { o0[r] = 0.f; o1[r] = 0.f; }
        #pragma unroll
        for (int jj = 0; jj < 2; jj++) {
            int cA = 2 * q + 16 * jj;
            float2 wA = *(const float2*)(sm + OFF_W4 + 2 * cA);
            float2 wB = *(const float2*)(sm + OFF_W4 + 2 * cA + 2);
            #pragma unroll
            for (int r = 0; r < 8; r++) {
                float a, b; unpack2(a3[jj][r], a, b);
                a = fmaxf(a, 0.f); b = fmaxf(b, 0.f);
                o0[r] = fmaf(a, wA.x, o0[r]);
                o1[r] = fmaf(a, wA.y, o1[r]);
                o0[r] = fmaf(b, wB.x, o0[r]);
                o1[r] = fmaf(b, wB.y, o1[r]);
            }
        }
        // reduce across the 8-lane group (full-warp shfl, all threads join)
        #pragma unroll
        for (int r = 0; r < 8; r++) {
            o0[r] += __shfl_xor_sync(0xffffffffu, o0[r], 1);
            o0[r] += __shfl_xor_sync(0xffffffffu, o0[r], 2);
            o0[r] += __shfl_xor_sync(0xffffffffu, o0[r], 4);
            o1[r] += __shfl_xor_sync(0xffffffffu, o1[r], 1);
            o1[r] += __shfl_xor_sync(0xffffffffu, o1[r], 2);
            o1[r] += __shfl_xor_sync(0xffffffffu, o1[r], 4);
        }
        if (active) {
            // lane q emits row q (static selects, no local-mem indexing)
            float s0 = (q == 0) ? o0[0] : (q == 1) ? o0[1] : (q == 2) ? o0[2] :
                       (q == 3) ? o0[3] : (q == 4) ? o0[4] : (q == 5) ? o0[5] :
                       (q == 6) ? o0[6] : o0[7];
            float s1 = (q == 0) ? o1[0] : (q == 1) ? o1[1] : (q == 2) ? o1[2] :
                       (q == 3) ? o1[3] : (q == 4) ? o1[4] : (q == 5) ? o1[5] :
                       (q == 6) ? o1[6] : o1[7];
            float2 ov = make_float2(s0 + sm[OFF_B4 + 0], s1 + sm[OFF_B4 + 1]);
            int row = row0 + q;
            if (row < MN) g_emb[row] = ov;
            else          g_qx[row - MN] = ov;
        }
        __syncwarp();
    }
}

// ---------------- kernel 2: per-node prob2 / has_child (query-independent) ---
__global__ void precompute_kernel(const float* __restrict__ node_classes,
                                  const int* __restrict__ children) {
    int i = blockIdx.x * blockDim.x + threadIdx.x;
    if (i >= MN) return;
    const int4* ch4 = (const int4*)children;
    int4 c0 = ch4[2 * i], c1 = ch4[2 * i + 1];
    int ci[8] = {c0.x, c0.y, c0.z, c0.w, c1.x, c1.y, c1.z, c1.w};
    float2 e = g_emb[i];
    float d[8]; bool any = false;
    #pragma unroll
    for (int k = 0; k < 8; k++) {
        int c = ci[k];
        if (c >= 0) {
            float2 ec = g_emb[c];
            d[k] = pdist(e.x, e.y, ec.x, ec.y);   // dist(emb[cur], c_emb)
            any = true;
        } else d[k] = F_BIG;
    }
    float4 r = make_float4(0.f, 0.f, 0.f, 0.f);
    if (any) {
        float mn = d[0];
        #pragma unroll
        for (int k = 1; k < 8; k++) mn = fminf(mn, d[k]);
        float S = 0.f, m0 = 0.f, m1 = 0.f;
        #pragma unroll
        for (int k = 0; k < 8; k++) {
            float ek = expf(-(d[k] - mn));
            S += ek;
            int c = ci[k];
            if (c >= 0) {
                m0 = fmaf(ek, node_classes[2 * c + 0], m0);
                m1 = fmaf(ek, node_classes[2 * c + 1], m1);
            }
        }
        m0 /= S; m1 /= S;
        r.x = logf(fmaxf(m0, 1e-30f));
        r.y = logf(fmaxf(m1, 1e-30f));
        r.z = 1.f;
    }
    g_node2[i] = r;
}

// ---------------- kernel 3: tree traversal (no smem, high occupancy) ---------
__global__ void __launch_bounds__(256)
traverse_kernel(const int* __restrict__ children, float* __restrict__ out) {
    const int q = blockIdx.x * 256 + threadIdx.x;   // grid covers NQ exactly
    const float2 qx = g_qx[q];
    const float q0 = qx.x, q1 = qx.y;
    const int4* ch4 = (const int4*)children;

    int cur = 0;
    float prob = 0.f, o0 = 0.f, o1 = 0.f;
    for (int t = 0; t < 16; t++) {
        int4 c0 = __ldg(ch4 + 2 * cur);
        int4 c1 = __ldg(ch4 + 2 * cur + 1);
        int ci[8] = {c0.x, c0.y, c0.z, c0.w, c1.x, c1.y, c1.z, c1.w};
        float2 e = g_emb[cur];
        float d0 = pdist(e.x, e.y, q0, q1);
        float d[8];
        #pragma unroll
        for (int k = 0; k < 8; k++) {
            int c = ci[k];
            if (c >= 0) {
                float2 ec = g_emb[c];
                d[k] = pdist(ec.x, ec.y, q0, q1);
            } else d[k] = F_BIG;
        }
        // argmax(log_softmax(-d)) == first-occurrence argmin(d)
        float best = d0; int bi = 0;
        #pragma unroll
        for (int k = 0; k < 8; k++) { if (d[k] < best) { best = d[k]; bi = k + 1; } }
        float S = __expf(-(d0 - best));
        #pragma unroll
        for (int k = 0; k < 8; k++) S += __expf(-(d[k] - best));  // pad: exp(-1e9)=0
        float mp = -__logf(S);     // max of log_softmax
        prob += mp;
        if (t == 0) prob += mp;    // source quirk: first iter adds max_prob twice
        if (bi == 0) {
            float4 n2 = g_node2[cur];
            if (n2.z != 0.f) { o0 = prob + n2.x; o1 = prob + n2.y; }
            else             { o0 = prob;        o1 = prob;        }
            break;
        }
        cur = ci[bi - 1];
    }
    ((float2*)out)[q] = make_float2(o0, o1);
}

// ---------------- launch ------------------------------------------------------
extern "C" void kernel_launch(void* const* d_in, const int* in_sizes, int n_in,
                              void* d_out, int out_size) {
    const float* x  = (const float*)d_in[0];
    const float* nd = (const float*)d_in[1];
    const float* nc = (const float*)d_in[2];
    const int*   ch = (const int*)  d_in[3];
    const float* W1 = (const float*)d_in[4];
    const float* b1 = (const float*)d_in[5];
    const float* W2 = (const float*)d_in[6];
    const float* b2 = (const float*)d_in[7];
    const float* W3 = (const float*)d_in[8];
    const float* b3 = (const float*)d_in[9];
    const float* W4 = (const float*)d_in[10];
    const float* b4 = (const float*)d_in[11];

    cudaFuncSetAttribute(mlp_all_kernel,
                         cudaFuncAttributeMaxDynamicSharedMemorySize, SMEM_BYTES);

    mlp_all_kernel<<<MLP_GRID, MLP_BLOCK, SMEM_BYTES>>>(x, nd,
                                                        W1, b1, W2, b2,
                                                        W3, b3, W4, b4);
    precompute_kernel<<<MN / 256, 256>>>(nc, ch);
    traverse_kernel<<<NQ / 256, 256>>>(ch, (float*)d_out);
}